// round 14
// baseline (speedup 1.0000x reference)
#include <cuda_runtime.h>
#include <cuda_bf16.h>
#include <stdint.h>

#define D     64
#define KCB   1024
#define MT    256          // rows per block
#define NTH   256          // 8 warps
#define CHC   64           // candidates per chunk
#define NCH   (KCB/CHC)    // 16

// ---------------- device globals ----------------
__device__ __align__(16) __nv_bfloat16 g_c0[KCB * D];   // permuted bf16 codebook
__device__ float g_cnorm[KCB];
__device__ float g_part[1024];
__device__ unsigned int g_done = 0;

// ---------------- smem layout (bytes) ----------------
#define OFF_XB    0                       // bf16 x tile: 256 rows * 128B
#define OFF_CS    32768                   // 3 bufs * 8KB ring
#define OFF_CN    57344                   // 1024 f32 exact cnorm (rescore)
#define OFF_XN    61440                   // 256 f32
#define OFF_SIDX  62464                   // 256 i32
#define OFF_SRED  63488                   // 8 f32 + last-block flag
#define SMEM_DYN  63552

__device__ __forceinline__ uint32_t smem_u32(const void* p) {
    uint32_t a;
    asm("{ .reg .u64 t; cvta.to.shared.u64 t, %1; cvt.u32.u64 %0, t; }"
        : "=r"(a) : "l"(p));
    return a;
}

#define LDS64(r0_, r1_, a) \
    asm("ld.shared.v2.b32 {%0,%1}, [%2];" : "=r"(r0_), "=r"(r1_) : "r"(a))

#define MMA_BF16(dd, aa, b0_, b1_) \
    asm("mma.sync.aligned.m16n8k16.row.col.f32.bf16.bf16.f32 " \
        "{%0,%1,%2,%3}, {%4,%5,%6,%7}, {%8,%9}, {%0,%1,%2,%3};" \
        : "+f"((dd)[0]), "+f"((dd)[1]), "+f"((dd)[2]), "+f"((dd)[3]) \
        : "r"((aa)[0]), "r"((aa)[1]), "r"((aa)[2]), "r"((aa)[3]), \
          "r"(b0_), "r"(b1_))

#define CP_ASYNC16(dst, src) \
    asm volatile("cp.async.cg.shared.global [%0], [%1], 16;" \
                 :: "r"(dst), "l"(src) : "memory")
#define CP_COMMIT() asm volatile("cp.async.commit_group;" ::: "memory")

// ---------------- prep: bf16 codebook (permuted) + exact cnorm ----------------
__global__ void vq_prep(const float* __restrict__ cb) {
    int i = blockIdx.x * blockDim.x + threadIdx.x;
    if (i < KCB * D) {
        int k = i >> 6, d = i & 63;
        float v = cb[i];
        __nv_bfloat16 h0 = __float2bfloat16_rn(v);
        int ks = d >> 4, w16 = d & 15;
        int hi8 = w16 >> 3, tig = (w16 & 7) >> 1, sub = d & 1;
        int pos = (4 * ks + tig) * 4 + hi8 * 2 + sub;
        g_c0[k * D + pos] = h0;
    }
    if (i < KCB) {
        float s = 0.f;
        #pragma unroll
        for (int d = 0; d < D; d++) {
            float v = cb[i * D + d];
            s = __fadd_rn(s, __fmul_rn(v, v));
        }
        g_cnorm[i] = s;
    }
}

// async copy chunk ch into ring buffer buf
__device__ __forceinline__ void issue_chunk(uint32_t cs_base_u32, int ch, int buf, int tid) {
    uint32_t dst_base = cs_base_u32 + (uint32_t)buf * 8192u;
    #pragma unroll
    for (int t = 0; t < 2; t++) {
        int j = tid + t * NTH;
        int cand = j >> 3;
        int b = j & 7;
        int bsw = b ^ ((cand & 3) << 1);
        const char* src = (const char*)g_c0 + ((ch * CHC + cand) * D + b * 8) * 2;
        uint32_t dst = dst_base + (uint32_t)cand * 128u + (uint32_t)bsw * 16u;
        CP_ASYNC16(dst, src);
    }
    CP_COMMIT();
}

// exact d2 with x row pre-loaded into registers (identical arithmetic to the
// R1-verified sequential FFMA formula)
__device__ __forceinline__ float exact_d2_reg(const float* __restrict__ cb,
                                              const float4* xr, float xn,
                                              const float* cn_s, int idx) {
    const float4* cr = (const float4*)(cb + (long long)idx * D);
    float acc = 0.f;
    #pragma unroll
    for (int j = 0; j < 16; j++) {
        float4 c4 = cr[j];
        float4 x4 = xr[j];
        acc = __fmaf_rn(x4.x, c4.x, acc);
        acc = __fmaf_rn(x4.y, c4.y, acc);
        acc = __fmaf_rn(x4.z, c4.z, acc);
        acc = __fmaf_rn(x4.w, c4.w, acc);
    }
    return __fadd_rn(__fmaf_rn(-2.0f, acc, xn), cn_s[idx]);
}

// sorted top-4 insert (pure key minmax)
__device__ __forceinline__ void ins4(int& t1, int& t2, int& t3, int& t4, int x) {
    int a = max(t1, x), b = min(t1, x); t1 = a;
    int c = max(t2, b), dd = min(t2, b); t2 = c;
    int e = max(t3, dd), f = min(t3, dd); t3 = e;
    t4 = max(t4, f);
}

// ---------------- main kernel ----------------
__global__ void __launch_bounds__(NTH, 3)
vq_main(const float* __restrict__ inp, const float* __restrict__ cb,
        float* __restrict__ out, int N, long long loss_off, long long idx_off,
        int nblocks, double inv_cnt) {
    extern __shared__ __align__(16) char sm[];
    const uint32_t sb = smem_u32(sm);

    const int tid = threadIdx.x;
    const int wid = tid >> 5;
    const int lane = tid & 31;
    const int g = lane >> 2;
    const int tig = lane & 3;
    const long long rowbase = (long long)blockIdx.x * MT;

    float* cn_s = (float*)(sm + OFF_CN);
    float* xn_s = (float*)(sm + OFF_XN);
    int*   sidx = (int*)(sm + OFF_SIDX);
    float* sred = (float*)(sm + OFF_SRED);
    int*   slast = (int*)(sm + OFF_SRED + 32);

    issue_chunk(sb + OFF_CS, 0, 0, tid);
    issue_chunk(sb + OFF_CS, 1, 1, tid);

    // ---- convert X -> bf16 permuted tile (paired dwords, STS.64) ----
    const float* gx = inp + rowbase * D;
    #pragma unroll
    for (int i = 0; i < MT * 16 / NTH; i++) {
        int e = tid + i * NTH;
        int row = e >> 4, u = e & 15;
        int ks = u >> 2, tg = u & 3;
        int d0 = ks * 16 + tg * 2;
        float2 va = *(const float2*)(gx + row * 64 + d0);
        float2 vb = *(const float2*)(gx + row * 64 + d0 + 8);
        __nv_bfloat162 ha = __floats2bfloat162_rn(va.x, va.y);
        __nv_bfloat162 hb = __floats2bfloat162_rn(vb.x, vb.y);
        int xr = (row & 3) << 2;
        char* dst = sm + OFF_XB + row * 128 + (u ^ xr) * 8;
        *(__nv_bfloat162*)dst = ha;
        *(__nv_bfloat162*)(dst + 4) = hb;
    }
    #pragma unroll
    for (int i = 0; i < KCB / NTH; i++) cn_s[tid + i * NTH] = g_cnorm[tid + i * NTH];

    // per-row exact xnorm (sequential mul-add over d, matches reference)
    {
        float s = 0.f;
        const float4* xr4 = (const float4*)(gx + tid * D);
        #pragma unroll
        for (int j = 0; j < 16; j++) {
            float4 v = xr4[j];
            s = __fadd_rn(s, __fmul_rn(v.x, v.x));
            s = __fadd_rn(s, __fmul_rn(v.y, v.y));
            s = __fadd_rn(s, __fmul_rn(v.z, v.z));
            s = __fadd_rn(s, __fmul_rn(v.w, v.w));
        }
        xn_s[tid] = s;
    }
    __syncthreads();

    uint32_t dwo[4];
    #pragma unroll
    for (int ks = 0; ks < 4; ks++)
        dwo[ks] = (uint32_t)(((4 * ks + tig) ^ ((g & 3) << 2)) * 8);

    // ---- hoist A fragments for the whole kernel ----
    uint32_t A0[2][4][4];
    const int r0 = wid * 32;
    #pragma unroll
    for (int at = 0; at < 2; at++) {
        uint32_t rlo = sb + OFF_XB + (uint32_t)(r0 + at * 16 + g) * 128u;
        uint32_t rhi = rlo + 8u * 128u;
        #pragma unroll
        for (int ks = 0; ks < 4; ks++) {
            LDS64(A0[at][ks][0], A0[at][ks][2], rlo + dwo[ks]);
            LDS64(A0[at][ks][1], A0[at][ks][3], rhi + dwo[ks]);
        }
    }

    // packed-key top-3 per (thread, row-slot); key = [value:22 | id:10]
    int k1[4], k2[4], k3[4];
    #pragma unroll
    for (int s = 0; s < 4; s++) { k1[s] = INT32_MIN; k2[s] = INT32_MIN; k3[s] = INT32_MIN; }

    // ---- chunk loop (3-buffer ring, one sync per chunk) ----
    for (int ch = 0; ch < NCH; ch++) {
        if (ch < 15) { asm volatile("cp.async.wait_group 1;" ::: "memory"); }
        else         { asm volatile("cp.async.wait_group 0;" ::: "memory"); }
        __syncthreads();
        if (ch + 2 < NCH) issue_chunk(sb + OFF_CS, ch + 2, (ch + 2) % 3, tid);

        const uint32_t cs = sb + OFF_CS + (uint32_t)(ch % 3) * 8192u;

        #pragma unroll
        for (int pass = 0; pass < 4; pass++) {
            // 4 MMA chains (2 at x 2 nt) -> acc 16 regs, occ-3 friendly
            float acc[2][2][4];
            #pragma unroll
            for (int at = 0; at < 2; at++)
                #pragma unroll
                for (int nt = 0; nt < 2; nt++)
                    #pragma unroll
                    for (int q = 0; q < 4; q++) acc[at][nt][q] = 0.f;

            #pragma unroll
            for (int ks = 0; ks < 4; ks++) {
                uint32_t B0[2][2];
                #pragma unroll
                for (int nt = 0; nt < 2; nt++) {
                    const uint32_t crow =
                        (uint32_t)((pass * 2 + nt) * 8 + g) * 128u + dwo[ks];
                    LDS64(B0[nt][0], B0[nt][1], cs + crow);
                }
                #pragma unroll
                for (int at = 0; at < 2; at++)
                    #pragma unroll
                    for (int nt = 0; nt < 2; nt++)
                        MMA_BF16(acc[at][nt], A0[at][ks], B0[nt][0], B0[nt][1]);
            }

            // ---- epilogue: 22-bit value | 10-bit id keys, top-3 insert ----
            #pragma unroll
            for (int at = 0; at < 2; at++) {
                #pragma unroll
                for (int nt = 0; nt < 2; nt++) {
                    const int idq = ch * 16 + pass * 4 + nt * 2;  // + q below
                    #pragma unroll
                    for (int sub = 0; sub < 2; sub++) {
                        const int s = at * 2 + sub;
                        #pragma unroll
                        for (int q = 0; q < 2; q++) {
                            int idv = ((idq + q) << 2) | tig;
                            int key = (__float_as_int(acc[at][nt][sub * 2 + q])
                                       & (int)0xFFFFFC00) | idv;
                            int m1 = max(k1[s], key);
                            int n1 = min(k1[s], key);
                            k1[s] = m1;
                            int m2 = max(k2[s], n1);
                            int n2 = min(k2[s], n1);
                            k2[s] = m2;
                            k3[s] = max(k3[s], n2);
                        }
                    }
                }
            }
        }
    }

    // ---- quad merge -> row-wide top-4; broadcast exact rescore of 4 ----
    const int qb = lane & ~3;
    #pragma unroll
    for (int s = 0; s < 4; s++) {
        int row = r0 + (s >> 1) * 16 + ((s & 1) << 3) + g;

        int t1 = INT32_MIN, t2 = INT32_MIN, t3 = INT32_MIN, t4 = INT32_MIN;
        int a0 = k1[s], a1 = k2[s], a2 = k3[s];
        #pragma unroll
        for (int t = 0; t < 4; t++) {
            int r0k = __shfl_sync(0xffffffffu, a0, qb + t);
            int r1k = __shfl_sync(0xffffffffu, a1, qb + t);
            int r2k = __shfl_sync(0xffffffffu, a2, qb + t);
            ins4(t1, t2, t3, t4, r0k);
            ins4(t1, t2, t3, t4, r1k);
            ins4(t1, t2, t3, t4, r2k);
        }

        // hoist x row into registers (same loads/order as before)
        const float4* gxr = (const float4*)(gx + row * D);
        float4 xr[16];
        #pragma unroll
        for (int j = 0; j < 16; j++) xr[j] = gxr[j];
        float xnv = xn_s[row];

        float wv = 3.4e38f; int wi = 0;
        int keys[4] = { t1, t2, t3, t4 };
        #pragma unroll
        for (int c = 0; c < 4; c++) {
            int id10 = keys[c] & 0x3FF;
            int tsrc = id10 & 3;
            int idq = id10 >> 2;                 // ch*16 + pass*4 + nt*2 + q
            int chh = idq >> 4;
            int pq = idq & 15;
            int gidx = chh * 64 + ((pq >> 2) * 2 + ((pq >> 1) & 1)) * 8
                     + 2 * tsrc + (pq & 1);
            float e = exact_d2_reg(cb, xr, xnv, cn_s, gidx);
            if (e < wv || (e == wv && gidx < wi)) { wv = e; wi = gidx; }
        }
        if (tig == 0) sidx[row] = wi;
    }
    __syncthreads();

    // ---- writeback: quantized_ste + loss partial (float4) ----
    float lsum = 0.f;
    const float4* gx4 = (const float4*)gx;
    const float4* cb4 = (const float4*)cb;
    float4* out4 = (float4*)(out + rowbase * D);
    #pragma unroll
    for (int i = 0; i < MT * 16 / NTH; i++) {
        int e = tid + i * NTH;
        int row = e >> 4, d4 = e & 15;
        int idx = sidx[row];
        float4 x4 = gx4[e];
        float4 c4 = cb4[idx * 16 + d4];
        float4 o;
        float dx = __fsub_rn(c4.x, x4.x); o.x = __fadd_rn(x4.x, dx);
        float dy = __fsub_rn(c4.y, x4.y); o.y = __fadd_rn(x4.y, dy);
        float dz = __fsub_rn(c4.z, x4.z); o.z = __fadd_rn(x4.z, dz);
        float dw = __fsub_rn(c4.w, x4.w); o.w = __fadd_rn(x4.w, dw);
        out4[e] = o;
        lsum = __fmaf_rn(dx, dx, lsum);
        lsum = __fmaf_rn(dy, dy, lsum);
        lsum = __fmaf_rn(dz, dz, lsum);
        lsum = __fmaf_rn(dw, dw, lsum);
    }
    if (idx_off >= 0) out[idx_off + rowbase + tid] = (float)sidx[tid];

    #pragma unroll
    for (int off = 16; off; off >>= 1)
        lsum += __shfl_xor_sync(0xffffffffu, lsum, off);
    if (lane == 0) sred[wid] = lsum;
    __syncthreads();
    if (tid == 0) {
        float s = 0.f;
        #pragma unroll
        for (int w = 0; w < NTH / 32; w++) s += sred[w];
        g_part[blockIdx.x] = s;
        __threadfence();
        unsigned int t = atomicAdd(&g_done, 1u);
        slast[0] = (t == (unsigned)(nblocks - 1)) ? 1 : 0;
    }
    __syncthreads();

    // ---- last block: final loss reduction (deterministic, fixed order) ----
    if (slast[0] && loss_off >= 0) {
        __shared__ double sd[NTH];
        double s = 0.0;
        for (int i = tid; i < nblocks; i += NTH) s += (double)g_part[i];
        sd[tid] = s;
        __syncthreads();
        for (int k = NTH / 2; k; k >>= 1) {
            if (tid < k) sd[tid] += sd[tid + k];
            __syncthreads();
        }
        if (tid == 0) {
            float m = (float)(sd[0] * inv_cnt);
            out[loss_off] = __fadd_rn(m, __fmul_rn(0.25f, m));
            g_done = 0;                    // reset for next graph replay
        }
    }
}

extern "C" void kernel_launch(void* const* d_in, const int* in_sizes, int n_in,
                              void* d_out, int out_size) {
    const float* inp = (const float*)d_in[0];
    const float* cb  = (const float*)d_in[1];
    float* out = (float*)d_out;

    const int N = in_sizes[0] / D;                 // 131072
    const long long sq = (long long)N * D;
    long long loss_off = -1, idx_off = -1;
    if ((long long)out_size >= sq + 1)     loss_off = sq;
    if ((long long)out_size >= sq + 1 + N) idx_off  = sq + 1;

    const int nb = N / MT;                         // 512

    cudaFuncSetAttribute(vq_main, cudaFuncAttributeMaxDynamicSharedMemorySize, SMEM_DYN);

    vq_prep<<<(KCB * D + 255) / 256, 256>>>(cb);
    vq_main<<<nb, NTH, SMEM_DYN>>>(inp, cb, out, N, loss_off, idx_off,
                                   nb, 1.0 / (double)((long long)N * D));
}

// round 15
// speedup vs baseline: 1.1690x; 1.1690x over previous
#include <cuda_runtime.h>
#include <cuda_bf16.h>
#include <stdint.h>

#define D     64
#define KCB   1024
#define MT    256          // rows per block
#define NTH   256          // 8 warps
#define CHC   64           // candidates per chunk
#define NCH   (KCB/CHC)    // 16

// ---------------- device globals ----------------
__device__ __align__(16) __nv_bfloat16 g_c0[KCB * D];   // permuted bf16 codebook
__device__ float g_cnorm[KCB];
__device__ float g_part[1024];
__device__ unsigned int g_done = 0;

// ---------------- smem layout (bytes) ----------------
#define OFF_XB    0                       // bf16 x tile: 256 rows * 128B
#define OFF_CS    32768                   // 3 bufs * 8KB ring
#define OFF_CN    57344                   // 1024 f32 exact cnorm (rescore)
#define OFF_XN    61440                   // 256 f32
#define OFF_SIDX  62464                   // 256 i32
#define OFF_SRED  63488                   // 8 f32 + last-block flag
#define SMEM_DYN  63552

__device__ __forceinline__ uint32_t smem_u32(const void* p) {
    uint32_t a;
    asm("{ .reg .u64 t; cvta.to.shared.u64 t, %1; cvt.u32.u64 %0, t; }"
        : "=r"(a) : "l"(p));
    return a;
}

#define LDS64(r0_, r1_, a) \
    asm("ld.shared.v2.b32 {%0,%1}, [%2];" : "=r"(r0_), "=r"(r1_) : "r"(a))

#define MMA_BF16(dd, aa, b0_, b1_) \
    asm("mma.sync.aligned.m16n8k16.row.col.f32.bf16.bf16.f32 " \
        "{%0,%1,%2,%3}, {%4,%5,%6,%7}, {%8,%9}, {%0,%1,%2,%3};" \
        : "+f"((dd)[0]), "+f"((dd)[1]), "+f"((dd)[2]), "+f"((dd)[3]) \
        : "r"((aa)[0]), "r"((aa)[1]), "r"((aa)[2]), "r"((aa)[3]), \
          "r"(b0_), "r"(b1_))

#define CP_ASYNC16(dst, src) \
    asm volatile("cp.async.cg.shared.global [%0], [%1], 16;" \
                 :: "r"(dst), "l"(src) : "memory")
#define CP_COMMIT() asm volatile("cp.async.commit_group;" ::: "memory")

// ---------------- prep: bf16 codebook (permuted) + exact cnorm ----------------
__global__ void vq_prep(const float* __restrict__ cb) {
    int i = blockIdx.x * blockDim.x + threadIdx.x;
    if (i < KCB * D) {
        int k = i >> 6, d = i & 63;
        float v = cb[i];
        __nv_bfloat16 h0 = __float2bfloat16_rn(v);
        int ks = d >> 4, w16 = d & 15;
        int hi8 = w16 >> 3, tig = (w16 & 7) >> 1, sub = d & 1;
        int pos = (4 * ks + tig) * 4 + hi8 * 2 + sub;
        g_c0[k * D + pos] = h0;
    }
    if (i < KCB) {
        float s = 0.f;
        #pragma unroll
        for (int d = 0; d < D; d++) {
            float v = cb[i * D + d];
            s = __fadd_rn(s, __fmul_rn(v, v));
        }
        g_cnorm[i] = s;
    }
}

// async copy chunk ch into ring buffer buf
__device__ __forceinline__ void issue_chunk(uint32_t cs_base_u32, int ch, int buf, int tid) {
    uint32_t dst_base = cs_base_u32 + (uint32_t)buf * 8192u;
    #pragma unroll
    for (int t = 0; t < 2; t++) {
        int j = tid + t * NTH;
        int cand = j >> 3;
        int b = j & 7;
        int bsw = b ^ ((cand & 3) << 1);
        const char* src = (const char*)g_c0 + ((ch * CHC + cand) * D + b * 8) * 2;
        uint32_t dst = dst_base + (uint32_t)cand * 128u + (uint32_t)bsw * 16u;
        CP_ASYNC16(dst, src);
    }
    CP_COMMIT();
}

// exact d2 with x row pre-loaded into registers (identical arithmetic to the
// R1-verified sequential FFMA formula)
__device__ __forceinline__ float exact_d2_reg(const float* __restrict__ cb,
                                              const float4* xr, float xn,
                                              const float* cn_s, int idx) {
    const float4* cr = (const float4*)(cb + (long long)idx * D);
    float acc = 0.f;
    #pragma unroll
    for (int j = 0; j < 16; j++) {
        float4 c4 = cr[j];
        float4 x4 = xr[j];
        acc = __fmaf_rn(x4.x, c4.x, acc);
        acc = __fmaf_rn(x4.y, c4.y, acc);
        acc = __fmaf_rn(x4.z, c4.z, acc);
        acc = __fmaf_rn(x4.w, c4.w, acc);
    }
    return __fadd_rn(__fmaf_rn(-2.0f, acc, xn), cn_s[idx]);
}

// sorted top-4 insert (pure key minmax)
__device__ __forceinline__ void ins4(int& t1, int& t2, int& t3, int& t4, int x) {
    int a = max(t1, x), b = min(t1, x); t1 = a;
    int c = max(t2, b), dd = min(t2, b); t2 = c;
    int e = max(t3, dd), f = min(t3, dd); t3 = e;
    t4 = max(t4, f);
}

// ---------------- main kernel ----------------
__global__ void __launch_bounds__(NTH, 2)
vq_main(const float* __restrict__ inp, const float* __restrict__ cb,
        float* __restrict__ out, int N, long long loss_off, long long idx_off,
        int nblocks, double inv_cnt) {
    extern __shared__ __align__(16) char sm[];
    const uint32_t sb = smem_u32(sm);

    const int tid = threadIdx.x;
    const int wid = tid >> 5;
    const int lane = tid & 31;
    const int g = lane >> 2;
    const int tig = lane & 3;
    const long long rowbase = (long long)blockIdx.x * MT;

    float* cn_s = (float*)(sm + OFF_CN);
    float* xn_s = (float*)(sm + OFF_XN);
    int*   sidx = (int*)(sm + OFF_SIDX);
    float* sred = (float*)(sm + OFF_SRED);
    int*   slast = (int*)(sm + OFF_SRED + 32);

    issue_chunk(sb + OFF_CS, 0, 0, tid);
    issue_chunk(sb + OFF_CS, 1, 1, tid);

    // ---- convert X -> bf16 permuted tile (paired dwords, STS.64) ----
    const float* gx = inp + rowbase * D;
    #pragma unroll
    for (int i = 0; i < MT * 16 / NTH; i++) {
        int e = tid + i * NTH;
        int row = e >> 4, u = e & 15;
        int ks = u >> 2, tg = u & 3;
        int d0 = ks * 16 + tg * 2;
        float2 va = *(const float2*)(gx + row * 64 + d0);
        float2 vb = *(const float2*)(gx + row * 64 + d0 + 8);
        __nv_bfloat162 ha = __floats2bfloat162_rn(va.x, va.y);
        __nv_bfloat162 hb = __floats2bfloat162_rn(vb.x, vb.y);
        int xr = (row & 3) << 2;
        char* dst = sm + OFF_XB + row * 128 + (u ^ xr) * 8;
        *(__nv_bfloat162*)dst = ha;
        *(__nv_bfloat162*)(dst + 4) = hb;
    }
    #pragma unroll
    for (int i = 0; i < KCB / NTH; i++) cn_s[tid + i * NTH] = g_cnorm[tid + i * NTH];

    // per-row exact xnorm (sequential mul-add over d, matches reference)
    {
        float s = 0.f;
        const float4* xr4 = (const float4*)(gx + tid * D);
        #pragma unroll
        for (int j = 0; j < 16; j++) {
            float4 v = xr4[j];
            s = __fadd_rn(s, __fmul_rn(v.x, v.x));
            s = __fadd_rn(s, __fmul_rn(v.y, v.y));
            s = __fadd_rn(s, __fmul_rn(v.z, v.z));
            s = __fadd_rn(s, __fmul_rn(v.w, v.w));
        }
        xn_s[tid] = s;
    }
    __syncthreads();

    uint32_t dwo[4];
    #pragma unroll
    for (int ks = 0; ks < 4; ks++)
        dwo[ks] = (uint32_t)(((4 * ks + tig) ^ ((g & 3) << 2)) * 8);

    // ---- hoist A fragments for the whole kernel ----
    uint32_t A0[2][4][4];
    const int r0 = wid * 32;
    #pragma unroll
    for (int at = 0; at < 2; at++) {
        uint32_t rlo = sb + OFF_XB + (uint32_t)(r0 + at * 16 + g) * 128u;
        uint32_t rhi = rlo + 8u * 128u;
        #pragma unroll
        for (int ks = 0; ks < 4; ks++) {
            LDS64(A0[at][ks][0], A0[at][ks][2], rlo + dwo[ks]);
            LDS64(A0[at][ks][1], A0[at][ks][3], rhi + dwo[ks]);
        }
    }

    // packed-key top-3 per (thread, row-slot); key = [value:22 | id:10]
    int k1[4], k2[4], k3[4];
    #pragma unroll
    for (int s = 0; s < 4; s++) { k1[s] = INT32_MIN; k2[s] = INT32_MIN; k3[s] = INT32_MIN; }

    // ---- chunk loop (3-buffer ring, one sync per chunk) ----
    for (int ch = 0; ch < NCH; ch++) {
        if (ch < 15) { asm volatile("cp.async.wait_group 1;" ::: "memory"); }
        else         { asm volatile("cp.async.wait_group 0;" ::: "memory"); }
        __syncthreads();
        if (ch + 2 < NCH) issue_chunk(sb + OFF_CS, ch + 2, (ch + 2) % 3, tid);

        const uint32_t cs = sb + OFF_CS + (uint32_t)(ch % 3) * 8192u;

        #pragma unroll
        for (int pass = 0; pass < 2; pass++) {
            // 8 independent accumulator chains (2 at x 4 nt) — R13 config
            float acc[2][4][4];
            #pragma unroll
            for (int at = 0; at < 2; at++)
                #pragma unroll
                for (int nt = 0; nt < 4; nt++)
                    #pragma unroll
                    for (int q = 0; q < 4; q++) acc[at][nt][q] = 0.f;

            #pragma unroll
            for (int ks = 0; ks < 4; ks++) {
                uint32_t B0[4][2];
                #pragma unroll
                for (int nt = 0; nt < 4; nt++) {
                    const uint32_t crow =
                        (uint32_t)((pass * 4 + nt) * 8 + g) * 128u + dwo[ks];
                    LDS64(B0[nt][0], B0[nt][1], cs + crow);
                }
                #pragma unroll
                for (int at = 0; at < 2; at++)
                    #pragma unroll
                    for (int nt = 0; nt < 4; nt++)
                        MMA_BF16(acc[at][nt], A0[at][ks], B0[nt][0], B0[nt][1]);
            }

            // ---- epilogue: 22-bit value | 10-bit id keys, top-3 insert ----
            #pragma unroll
            for (int at = 0; at < 2; at++) {
                #pragma unroll
                for (int nt = 0; nt < 4; nt++) {
                    const int idq = ch * 16 + pass * 8 + nt * 2;  // + q below
                    #pragma unroll
                    for (int sub = 0; sub < 2; sub++) {
                        const int s = at * 2 + sub;
                        #pragma unroll
                        for (int q = 0; q < 2; q++) {
                            int idv = ((idq + q) << 2) | tig;
                            int key = (__float_as_int(acc[at][nt][sub * 2 + q])
                                       & (int)0xFFFFFC00) | idv;
                            int m1 = max(k1[s], key);
                            int n1 = min(k1[s], key);
                            k1[s] = m1;
                            int m2 = max(k2[s], n1);
                            int n2 = min(k2[s], n1);
                            k2[s] = m2;
                            k3[s] = max(k3[s], n2);
                        }
                    }
                }
            }
        }
    }

    // ---- quad merge -> row-wide top-4; ONE exact rescore per quad lane ----
    const int qb = lane & ~3;
    #pragma unroll
    for (int s = 0; s < 4; s++) {
        int row = r0 + (s >> 1) * 16 + ((s & 1) << 3) + g;

        int t1 = INT32_MIN, t2 = INT32_MIN, t3 = INT32_MIN, t4 = INT32_MIN;
        int a0 = k1[s], a1 = k2[s], a2 = k3[s];
        #pragma unroll
        for (int t = 0; t < 4; t++) {
            int r0k = __shfl_sync(0xffffffffu, a0, qb + t);
            int r1k = __shfl_sync(0xffffffffu, a1, qb + t);
            int r2k = __shfl_sync(0xffffffffu, a2, qb + t);
            ins4(t1, t2, t3, t4, r0k);
            ins4(t1, t2, t3, t4, r1k);
            ins4(t1, t2, t3, t4, r2k);
        }

        // this lane rescores exactly one of the row-wide top-4 (its tig-th)
        int mykey = (tig == 0) ? t1 : (tig == 1) ? t2 : (tig == 2) ? t3 : t4;
        int id10 = mykey & 0x3FF;
        int tsrc = id10 & 3;
        int idq = id10 >> 2;                 // ch*16 + pass*8 + nt*2 + q
        int chh = idq >> 4;
        int pq = idq & 15;
        int gidx = chh * 64 + ((pq >> 3) * 4 + ((pq >> 1) & 3)) * 8
                 + 2 * tsrc + (pq & 1);

        // hoist x row into registers (same loads/order as before)
        const float4* gxr = (const float4*)(gx + row * D);
        float4 xr[16];
        #pragma unroll
        for (int j = 0; j < 16; j++) xr[j] = gxr[j];
        float xnv = xn_s[row];

        float wv = exact_d2_reg(cb, xr, xnv, cn_s, gidx);
        int wi = gidx;
        // exact quad reduce: min value, lowest index on ties
        #pragma unroll
        for (int off = 1; off < 4; off <<= 1) {
            float ov = __shfl_xor_sync(0xffffffffu, wv, off);
            int   oi = __shfl_xor_sync(0xffffffffu, wi, off);
            if (ov < wv || (ov == wv && oi < wi)) { wv = ov; wi = oi; }
        }
        if (tig == 0) sidx[row] = wi;
    }
    __syncthreads();

    // ---- writeback: quantized_ste + loss partial (float4) ----
    float lsum = 0.f;
    const float4* gx4 = (const float4*)gx;
    const float4* cb4 = (const float4*)cb;
    float4* out4 = (float4*)(out + rowbase * D);
    #pragma unroll
    for (int i = 0; i < MT * 16 / NTH; i++) {
        int e = tid + i * NTH;
        int row = e >> 4, d4 = e & 15;
        int idx = sidx[row];
        float4 x4 = gx4[e];
        float4 c4 = cb4[idx * 16 + d4];
        float4 o;
        float dx = __fsub_rn(c4.x, x4.x); o.x = __fadd_rn(x4.x, dx);
        float dy = __fsub_rn(c4.y, x4.y); o.y = __fadd_rn(x4.y, dy);
        float dz = __fsub_rn(c4.z, x4.z); o.z = __fadd_rn(x4.z, dz);
        float dw = __fsub_rn(c4.w, x4.w); o.w = __fadd_rn(x4.w, dw);
        out4[e] = o;
        lsum = __fmaf_rn(dx, dx, lsum);
        lsum = __fmaf_rn(dy, dy, lsum);
        lsum = __fmaf_rn(dz, dz, lsum);
        lsum = __fmaf_rn(dw, dw, lsum);
    }
    if (idx_off >= 0) out[idx_off + rowbase + tid] = (float)sidx[tid];

    #pragma unroll
    for (int off = 16; off; off >>= 1)
        lsum += __shfl_xor_sync(0xffffffffu, lsum, off);
    if (lane == 0) sred[wid] = lsum;
    __syncthreads();
    if (tid == 0) {
        float s = 0.f;
        #pragma unroll
        for (int w = 0; w < NTH / 32; w++) s += sred[w];
        g_part[blockIdx.x] = s;
        __threadfence();
        unsigned int t = atomicAdd(&g_done, 1u);
        slast[0] = (t == (unsigned)(nblocks - 1)) ? 1 : 0;
    }
    __syncthreads();

    // ---- last block: final loss reduction (deterministic, fixed order) ----
    if (slast[0] && loss_off >= 0) {
        __shared__ double sd[NTH];
        double s = 0.0;
        for (int i = tid; i < nblocks; i += NTH) s += (double)g_part[i];
        sd[tid] = s;
        __syncthreads();
        for (int k = NTH / 2; k; k >>= 1) {
            if (tid < k) sd[tid] += sd[tid + k];
            __syncthreads();
        }
        if (tid == 0) {
            float m = (float)(sd[0] * inv_cnt);
            out[loss_off] = __fadd_rn(m, __fmul_rn(0.25f, m));
            g_done = 0;                    // reset for next graph replay
        }
    }
}

extern "C" void kernel_launch(void* const* d_in, const int* in_sizes, int n_in,
                              void* d_out, int out_size) {
    const float* inp = (const float*)d_in[0];
    const float* cb  = (const float*)d_in[1];
    float* out = (float*)d_out;

    const int N = in_sizes[0] / D;                 // 131072
    const long long sq = (long long)N * D;
    long long loss_off = -1, idx_off = -1;
    if ((long long)out_size >= sq + 1)     loss_off = sq;
    if ((long long)out_size >= sq + 1 + N) idx_off  = sq + 1;

    const int nb = N / MT;                         // 512

    cudaFuncSetAttribute(vq_main, cudaFuncAttributeMaxDynamicSharedMemorySize, SMEM_DYN);

    vq_prep<<<(KCB * D + 255) / 256, 256>>>(cb);
    vq_main<<<nb, NTH, SMEM_DYN>>>(inp, cb, out, N, loss_off, idx_off,
                                   nb, 1.0 / (double)((long long)N * D));
}